// round 4
// baseline (speedup 1.0000x reference)
#include <cuda_runtime.h>

// Problem dims
#define B_   1024
#define N_   64
#define T_   2048
#define D_   256
#define H_   8
#define C_   64
#define HC_  512
#define E_   1024
#define OUT_ 6
#define M_   (B_ * N_)   // 65536 rows for the big GEMM

// Scratch (no allocations allowed -> __device__ globals)
__device__ float g_Xp[(size_t)M_ * D_];        // 64 MB : X @ Wp + bp
__device__ float g_Q [(size_t)B_ * H_ * N_ * C_];
__device__ float g_K [(size_t)B_ * H_ * N_ * C_];
__device__ float g_V [(size_t)B_ * H_ * N_ * C_];
__device__ float g_SK[(size_t)B_ * H_ * N_ * C_];
__device__ float g_G [(size_t)B_ * HC_];       // graph representation
__device__ int   g_cnt[N_ * N_];               // edge multiplicity matrix

// ---------------------------------------------------------------------------
// K0: dense edge-count matrix cnt[dst][src] from edge_index.
// Dtype-robust: the reference declares int64 but JAX default config downcasts
// to int32. Detect on device: if the buffer is int64, every odd 32-bit word is
// a zero high-half (values < 64); if int32, odd words are random in [0,64).
// ---------------------------------------------------------------------------
__global__ void k_cnt(const int* __restrict__ ei) {
    __shared__ int odd_nz;
    int t = threadIdx.x;     // blockDim = 1024 = E_
    if (t == 0) odd_nz = 0;
    for (int i = t; i < N_ * N_; i += blockDim.x) g_cnt[i] = 0;
    __syncthreads();
    if (ei[2 * t + 1] != 0) atomicOr(&odd_nz, 1);
    __syncthreads();
    int s, d;
    if (odd_nz) {            // int32 layout: [src[E], dst[E]]
        s = ei[t] & 63;
        d = ei[E_ + t] & 63;
    } else {                 // int64 layout: take low words
        s = ei[2 * t] & 63;
        d = ei[2 * (E_ + t)] & 63;
    }
    atomicAdd(&g_cnt[d * N_ + s], 1);
}

// ---------------------------------------------------------------------------
// K1: Xp = X @ Wp + bp   ([65536 x 2048] @ [2048 x 256])
// BM=64, BN=256, BK=16; 256 threads; 8x8 microtile per thread.
// ---------------------------------------------------------------------------
__global__ __launch_bounds__(256) void k_proj1(const float* __restrict__ X,
                                               const float* __restrict__ Wp,
                                               const float* __restrict__ bp) {
    __shared__ float As[64 * 16];    // [m][k]
    __shared__ float Bs[16 * 256];   // [k][n]

    const int m0 = blockIdx.x * 64;
    const int t  = threadIdx.x;
    const int tx = t & 31;
    const int ty = t >> 5;

    float acc[8][8];
#pragma unroll
    for (int r = 0; r < 8; r++)
#pragma unroll
        for (int j = 0; j < 8; j++) acc[r][j] = 0.f;

    const int am = t >> 2;
    const int ak = (t & 3) << 2;

    for (int k0 = 0; k0 < T_; k0 += 16) {
        {
            float4 v = *(const float4*)(X + (size_t)(m0 + am) * T_ + k0 + ak);
            *(float4*)(As + am * 16 + ak) = v;
        }
#pragma unroll
        for (int r = 0; r < 4; r++) {
            int f  = t + r * 256;
            int kk = f >> 6;
            int c4 = (f & 63) << 2;
            float4 v = *(const float4*)(Wp + (size_t)(k0 + kk) * D_ + c4);
            *(float4*)(Bs + kk * 256 + c4) = v;
        }
        __syncthreads();

#pragma unroll
        for (int kk = 0; kk < 16; kk++) {
            float a[8];
#pragma unroll
            for (int r = 0; r < 8; r++) a[r] = As[(ty * 8 + r) * 16 + kk];
            float4 b0 = *(float4*)(Bs + kk * 256 + tx * 8);
            float4 b1 = *(float4*)(Bs + kk * 256 + tx * 8 + 4);
            float bb[8] = {b0.x, b0.y, b0.z, b0.w, b1.x, b1.y, b1.z, b1.w};
#pragma unroll
            for (int r = 0; r < 8; r++)
#pragma unroll
                for (int j = 0; j < 8; j++) acc[r][j] += a[r] * bb[j];
        }
        __syncthreads();
    }

    float4 bb0 = *(const float4*)(bp + tx * 8);
    float4 bb1 = *(const float4*)(bp + tx * 8 + 4);
    float bia[8] = {bb0.x, bb0.y, bb0.z, bb0.w, bb1.x, bb1.y, bb1.z, bb1.w};
#pragma unroll
    for (int r = 0; r < 8; r++) {
        float* dst = g_Xp + (size_t)(m0 + ty * 8 + r) * D_ + tx * 8;
        *(float4*)dst = make_float4(acc[r][0] + bia[0], acc[r][1] + bia[1],
                                    acc[r][2] + bia[2], acc[r][3] + bia[3]);
        *(float4*)(dst + 4) = make_float4(acc[r][4] + bia[4], acc[r][5] + bia[5],
                                          acc[r][6] + bia[6], acc[r][7] + bia[7]);
    }
}

// ---------------------------------------------------------------------------
// K1b: QKVS = Xp @ [Wq|Wk|Wv|Ws] + bias  ([65536 x 256] @ [256 x 2048])
// Grid (1024 row tiles, 8 col tiles of 256). Each col tile lies entirely in
// one of the 4 weight matrices. Output scattered to per-(b,h) 64x64 tiles.
// ---------------------------------------------------------------------------
__global__ __launch_bounds__(256) void k_proj2(
    const float* __restrict__ Wq, const float* __restrict__ bq,
    const float* __restrict__ Wk, const float* __restrict__ bk,
    const float* __restrict__ Wv, const float* __restrict__ bv,
    const float* __restrict__ Ws, const float* __restrict__ bs) {
    __shared__ float As[64 * 16];
    __shared__ float Bs[16 * 256];

    const int m0 = blockIdx.x * 64;
    const int ct = blockIdx.y;            // 0..7
    const int proj = ct >> 1;
    const int lcb  = (ct & 1) * 256;      // base col within the 512-wide proj

    const float* Wsel = (proj == 0) ? Wq : (proj == 1) ? Wk : (proj == 2) ? Wv : Ws;
    const float* bsel = (proj == 0) ? bq : (proj == 1) ? bk : (proj == 2) ? bv : bs;
    float* Dsel = (proj == 0) ? g_Q : (proj == 1) ? g_K : (proj == 2) ? g_V : g_SK;

    const int t  = threadIdx.x;
    const int tx = t & 31;
    const int ty = t >> 5;

    float acc[8][8];
#pragma unroll
    for (int r = 0; r < 8; r++)
#pragma unroll
        for (int j = 0; j < 8; j++) acc[r][j] = 0.f;

    const int am = t >> 2;
    const int ak = (t & 3) << 2;

    for (int k0 = 0; k0 < D_; k0 += 16) {
        {
            float4 v = *(const float4*)(g_Xp + (size_t)(m0 + am) * D_ + k0 + ak);
            *(float4*)(As + am * 16 + ak) = v;
        }
#pragma unroll
        for (int r = 0; r < 4; r++) {
            int f  = t + r * 256;
            int kk = f >> 6;
            int c4 = (f & 63) << 2;
            float4 v = *(const float4*)(Wsel + (size_t)(k0 + kk) * HC_ + lcb + c4);
            *(float4*)(Bs + kk * 256 + c4) = v;
        }
        __syncthreads();

#pragma unroll
        for (int kk = 0; kk < 16; kk++) {
            float a[8];
#pragma unroll
            for (int r = 0; r < 8; r++) a[r] = As[(ty * 8 + r) * 16 + kk];
            float4 b0 = *(float4*)(Bs + kk * 256 + tx * 8);
            float4 b1 = *(float4*)(Bs + kk * 256 + tx * 8 + 4);
            float bb[8] = {b0.x, b0.y, b0.z, b0.w, b1.x, b1.y, b1.z, b1.w};
#pragma unroll
            for (int r = 0; r < 8; r++)
#pragma unroll
                for (int j = 0; j < 8; j++) acc[r][j] += a[r] * bb[j];
        }
        __syncthreads();
    }

    // Epilogue: bias + scatter to [(b*H + h)*N + n]*C + c tiles.
    const int lc0 = lcb + tx * 8;         // col within proj (0..504)
    const int h   = lc0 >> 6;             // fixed per thread
    const int c0  = lc0 & 63;             // multiple of 8
    float4 bb0 = *(const float4*)(bsel + lc0);
    float4 bb1 = *(const float4*)(bsel + lc0 + 4);
    float bia[8] = {bb0.x, bb0.y, bb0.z, bb0.w, bb1.x, bb1.y, bb1.z, bb1.w};
#pragma unroll
    for (int r = 0; r < 8; r++) {
        int m = m0 + ty * 8 + r;
        int b = m >> 6, n = m & 63;
        float* dst = Dsel + (((size_t)(b * H_ + h)) * N_ + n) * C_ + c0;
        *(float4*)dst = make_float4(acc[r][0] + bia[0], acc[r][1] + bia[1],
                                    acc[r][2] + bia[2], acc[r][3] + bia[3]);
        *(float4*)(dst + 4) = make_float4(acc[r][4] + bia[4], acc[r][5] + bia[5],
                                          acc[r][6] + bia[6], acc[r][7] + bia[7]);
    }
}

// ---------------------------------------------------------------------------
// K2: attention per (b,h). One CTA (256 threads) per head-tile, 48 KB smem.
// Dense count-weighted attention == reference segment softmax over edges.
// ---------------------------------------------------------------------------
__global__ __launch_bounds__(256) void k_attn2() {
    extern __shared__ float sm[];
    float* qs = sm;            // 4096 floats: q tile (later node_out)
    float* kv = sm + 4096;     // 4096 floats: k tile, then v tile
    float* Ss = sm + 8192;     // 4096 floats: scores -> normalized weights

    const int hb = blockIdx.x;          // hb = b*H + h
    const int b  = hb >> 3;
    const int h  = hb & 7;
    const size_t base = (size_t)hb * (N_ * C_);
    const int t = threadIdx.x;

    // Load q, k tiles (16 KB each)
    for (int f = t; f < 1024; f += 256) {
        ((float4*)qs)[f] = ((const float4*)(g_Q + base))[f];
        ((float4*)kv)[f] = ((const float4*)(g_K + base))[f];
    }
    __syncthreads();

    const int i  = t >> 2;              // row 0..63
    const int g4 = t & 3;

    // ---- scores S[i][j] = dot(q_i, k_j) / 8 ; 16 j's per thread ----
    {
        const int j0 = g4 << 4;
        float acc[16];
#pragma unroll
        for (int jj = 0; jj < 16; jj++) acc[jj] = 0.f;
#pragma unroll
        for (int c4 = 0; c4 < 16; c4++) {
            float4 q = *(float4*)(qs + i * 64 + c4 * 4);
#pragma unroll
            for (int jj = 0; jj < 16; jj++) {
                float4 k4 = *(float4*)(kv + (j0 + jj) * 64 + c4 * 4);
                acc[jj] += q.x * k4.x + q.y * k4.y + q.z * k4.z + q.w * k4.w;
            }
        }
#pragma unroll
        for (int jj = 0; jj < 16; jj++)
            Ss[i * 64 + j0 + jj] = acc[jj] * 0.125f;
    }
    __syncthreads();

    // ---- overwrite k with v (overlaps softmax latency) ----
    for (int f = t; f < 1024; f += 256)
        ((float4*)kv)[f] = ((const float4*)(g_V + base))[f];

    // ---- count-weighted masked softmax, denom folded in ----
    {
        const int w = t >> 5, l = t & 31;
        for (int rr = 0; rr < 8; rr++) {
            int r = w * 8 + rr;
            float s1 = Ss[r * 64 + l], s2 = Ss[r * 64 + l + 32];
            int   c1 = g_cnt[r * 64 + l], c2 = g_cnt[r * 64 + l + 32];
            float v1 = c1 ? s1 : -1e30f;
            float v2 = c2 ? s2 : -1e30f;
            float m = fmaxf(v1, v2);
#pragma unroll
            for (int o = 16; o; o >>= 1)
                m = fmaxf(m, __shfl_xor_sync(0xffffffffu, m, o));
            if (m < -1e29f) m = 0.f;    // row with no incoming edges
            float a1 = c1 ? (float)c1 * __expf(s1 - m) : 0.f;
            float a2 = c2 ? (float)c2 * __expf(s2 - m) : 0.f;
            float su = a1 + a2;
#pragma unroll
            for (int o = 16; o; o >>= 1)
                su += __shfl_xor_sync(0xffffffffu, su, o);
            float inv = 1.f / (su + 1e-16f);
            Ss[r * 64 + l]      = a1 * inv;
            Ss[r * 64 + l + 32] = a2 * inv;
        }
    }
    __syncthreads();

    // ---- node = A_hat @ v + skip ; store into qs ----
    {
        const int c0 = g4 << 4;
        float a16[16];
#pragma unroll
        for (int jj = 0; jj < 16; jj++) a16[jj] = 0.f;
        for (int j = 0; j < 64; j++) {
            float wgt = Ss[i * 64 + j];
#pragma unroll
            for (int cc = 0; cc < 4; cc++) {
                float4 v4 = *(float4*)(kv + j * 64 + c0 + cc * 4);
                a16[cc * 4 + 0] += wgt * v4.x;
                a16[cc * 4 + 1] += wgt * v4.y;
                a16[cc * 4 + 2] += wgt * v4.z;
                a16[cc * 4 + 3] += wgt * v4.w;
            }
        }
        const float* skp = g_SK + base + i * 64 + c0;
#pragma unroll
        for (int cc = 0; cc < 4; cc++) {
            float4 s4 = *(const float4*)(skp + cc * 4);
            float4 o4 = make_float4(a16[cc * 4 + 0] + s4.x, a16[cc * 4 + 1] + s4.y,
                                    a16[cc * 4 + 2] + s4.z, a16[cc * 4 + 3] + s4.w);
            *(float4*)(qs + i * 64 + c0 + cc * 4) = o4;
        }
    }
    __syncthreads();

    // ---- column mean over 64 nodes -> g_G[b, h*64 + c] ----
    {
        const int c = t & 63, ig = t >> 6;
        float s = 0.f;
#pragma unroll
        for (int r = 0; r < 16; r++) s += qs[(ig * 16 + r) * 64 + c];
        Ss[ig * 64 + c] = s;
        __syncthreads();
        if (t < 64) {
            float tot = Ss[t] + Ss[64 + t] + Ss[128 + t] + Ss[192 + t];
            g_G[(size_t)b * HC_ + h * C_ + t] = tot * (1.f / 64.f);
        }
    }
}

// ---------------------------------------------------------------------------
// K3: out[b] = G[b] @ Wr + br   ([1024 x 512] @ [512 x 6])
// ---------------------------------------------------------------------------
__global__ __launch_bounds__(192) void k_out(const float* __restrict__ Wr,
                                             const float* __restrict__ br,
                                             float* __restrict__ out) {
    int b = blockIdx.x;
    int o = threadIdx.x >> 5;
    int l = threadIdx.x & 31;
    float s = 0.f;
    for (int c = l; c < HC_; c += 32)
        s += g_G[(size_t)b * HC_ + c] * Wr[c * OUT_ + o];
#pragma unroll
    for (int off = 16; off; off >>= 1)
        s += __shfl_xor_sync(0xffffffffu, s, off);
    if (l == 0) out[b * OUT_ + o] = s + br[o];
}

// ---------------------------------------------------------------------------
extern "C" void kernel_launch(void* const* d_in, const int* in_sizes, int n_in,
                              void* d_out, int out_size) {
    const float* X  = (const float*)d_in[0];
    const int*   ei = (const int*)d_in[1];   // dtype auto-detected on device
    const float* Wp = (const float*)d_in[2];
    const float* bp = (const float*)d_in[3];
    const float* Wq = (const float*)d_in[4];
    const float* bq = (const float*)d_in[5];
    const float* Wk = (const float*)d_in[6];
    const float* bk = (const float*)d_in[7];
    const float* Wv = (const float*)d_in[8];
    const float* bv = (const float*)d_in[9];
    const float* Ws = (const float*)d_in[10];
    const float* bs = (const float*)d_in[11];
    const float* Wr = (const float*)d_in[12];
    const float* br = (const float*)d_in[13];
    float* out = (float*)d_out;

    k_cnt<<<1, 1024>>>(ei);
    k_proj1<<<M_ / 64, 256>>>(X, Wp, bp);
    k_proj2<<<dim3(1024, 8), 256>>>(Wq, bq, Wk, bk, Wv, bv, Ws, bs);
    k_attn2<<<B_ * H_, 256, 49152>>>();
    k_out<<<B_, 192>>>(Wr, br, out);
}

// round 6
// speedup vs baseline: 1.7664x; 1.7664x over previous
#include <cuda_runtime.h>
#include <cuda_bf16.h>

// Problem dims
#define B_   1024
#define N_   64
#define T_   2048
#define D_   256
#define H_   8
#define C_   64
#define HC_  512
#define E_   1024
#define OUT_ 6
#define M_   (B_ * N_)

#define PADK 20   // uint words per smem row: 16 data words (32 bf16) + 4 pad

// ---------------- device scratch (no allocations allowed) -------------------
// Split bf16 weights, pre-transposed to [n][k], packed as bf16 pairs along k.
__device__ unsigned g_WpT_h[D_ * (T_ / 2)];      // [256][1024] words
__device__ unsigned g_WpT_l[D_ * (T_ / 2)];
__device__ unsigned g_WcT_h[(4 * HC_) * (D_ / 2)]; // [2048 cols][128] words
__device__ unsigned g_WcT_l[(4 * HC_) * (D_ / 2)];
// Xp split bf16, [m][k] packed pairs along k: [65536][128] words
__device__ unsigned g_Xph[(size_t)M_ * (D_ / 2)];
__device__ unsigned g_Xpl[(size_t)M_ * (D_ / 2)];
// Attention operands (fp32) and outputs
__device__ float g_Q [(size_t)B_ * H_ * N_ * C_];
__device__ float g_K [(size_t)B_ * H_ * N_ * C_];
__device__ float g_V [(size_t)B_ * H_ * N_ * C_];
__device__ float g_SK[(size_t)B_ * H_ * N_ * C_];
__device__ float g_G [(size_t)B_ * HC_];
__device__ int   g_cnt[N_ * N_];

// ---------------- helpers ---------------------------------------------------
__device__ __forceinline__ void bsplit(float v, unsigned short& h, unsigned short& l) {
    __nv_bfloat16 bh = __float2bfloat16(v);
    float r = v - __bfloat162float(bh);
    __nv_bfloat16 bl = __float2bfloat16(r);
    h = __bfloat16_as_ushort(bh);
    l = __bfloat16_as_ushort(bl);
}
__device__ __forceinline__ unsigned pack2(unsigned short a, unsigned short b) {
    return (unsigned)a | ((unsigned)b << 16);
}
__device__ __forceinline__ void mma16816(float* c, const unsigned* a, const unsigned* b) {
    asm volatile(
        "mma.sync.aligned.m16n8k16.row.col.f32.bf16.bf16.f32 "
        "{%0,%1,%2,%3}, {%4,%5,%6,%7}, {%8,%9}, {%0,%1,%2,%3};"
        : "+f"(c[0]), "+f"(c[1]), "+f"(c[2]), "+f"(c[3])
        : "r"(a[0]), "r"(a[1]), "r"(a[2]), "r"(a[3]), "r"(b[0]), "r"(b[1]));
}

// ---------------- K0: edge-count matrix (dtype-robust) ----------------------
__global__ void k_cnt(const int* __restrict__ ei) {
    __shared__ int odd_nz;
    int t = threadIdx.x;  // 1024 = E_
    if (t == 0) odd_nz = 0;
    for (int i = t; i < N_ * N_; i += blockDim.x) g_cnt[i] = 0;
    __syncthreads();
    if (ei[2 * t + 1] != 0) atomicOr(&odd_nz, 1);
    __syncthreads();
    int s, d;
    if (odd_nz) { s = ei[t] & 63; d = ei[E_ + t] & 63; }
    else        { s = ei[2 * t] & 63; d = ei[2 * (E_ + t)] & 63; }
    atomicAdd(&g_cnt[d * N_ + s], 1);
}

// ---------------- prep: split + transpose weights ---------------------------
// Wp [2048][256] -> WpT [n=256][k pairs=1024]
__global__ __launch_bounds__(256) void k_prep_wp(const float* __restrict__ Wp) {
    int idx = blockIdx.x * 256 + threadIdx.x;     // 256*1024
    int n = idx >> 10, kw = idx & 1023, k = kw * 2;
    float v0 = Wp[(size_t)k * D_ + n];
    float v1 = Wp[(size_t)(k + 1) * D_ + n];
    unsigned short h0, l0, h1, l1;
    bsplit(v0, h0, l0); bsplit(v1, h1, l1);
    g_WpT_h[idx] = pack2(h0, h1);
    g_WpT_l[idx] = pack2(l0, l1);
}
// W{q,k,v,s} [256][512] -> WcT [col=2048][k pairs=128], col = proj*512 + wc
__global__ __launch_bounds__(256) void k_prep_wc(
    const float* __restrict__ Wq, const float* __restrict__ Wk,
    const float* __restrict__ Wv, const float* __restrict__ Ws) {
    int idx = blockIdx.x * 256 + threadIdx.x;     // 2048*128
    int col = idx >> 7, kw = idx & 127, k = kw * 2;
    int proj = col >> 9, wc = col & 511;
    const float* W = (proj == 0) ? Wq : (proj == 1) ? Wk : (proj == 2) ? Wv : Ws;
    float v0 = W[(size_t)k * HC_ + wc];
    float v1 = W[(size_t)(k + 1) * HC_ + wc];
    unsigned short h0, l0, h1, l1;
    bsplit(v0, h0, l0); bsplit(v1, h1, l1);
    g_WcT_h[idx] = pack2(h0, h1);
    g_WcT_l[idx] = pack2(l0, l1);
}

// ---------------- K1: Xp = X @ Wp + bp  (bf16x3 tensor-core) ----------------
// BM=128, BN=128, BK=32; 256 thr = 8 warps (2m x 4n); warp tile 64m x 32n.
__global__ __launch_bounds__(256) void k_gemm1(const float* __restrict__ X,
                                               const float* __restrict__ bp) {
    __shared__ unsigned Ah[128 * PADK], Al[128 * PADK];
    __shared__ unsigned Bh[128 * PADK], Bl[128 * PADK];

    const int m0 = blockIdx.x * 128, n0 = blockIdx.y * 128;
    const int t = threadIdx.x, lane = t & 31, w = t >> 5;
    const int wm = w >> 2, wn = w & 3;
    const int g = lane >> 2, t4 = lane & 3;

    float acc[4][4][4];
#pragma unroll
    for (int i = 0; i < 4; i++)
#pragma unroll
        for (int j = 0; j < 4; j++)
#pragma unroll
            for (int q = 0; q < 4; q++) acc[i][j][q] = 0.f;

    float4 a_st[4];
    unsigned bh_st[8], bl_st[8];

    // prefetch iter 0
#pragma unroll
    for (int j = 0; j < 4; j++) {
        int e = t + j * 256, row = e >> 3, kq = e & 7;
        a_st[j] = *(const float4*)(X + (size_t)(m0 + row) * T_ + kq * 4);
    }
#pragma unroll
    for (int j = 0; j < 8; j++) {
        int wd = t + j * 256, n = wd >> 4, kw = wd & 15;
        bh_st[j] = g_WpT_h[(size_t)(n0 + n) * (T_ / 2) + kw];
        bl_st[j] = g_WpT_l[(size_t)(n0 + n) * (T_ / 2) + kw];
    }

    for (int it = 0; it < T_ / 32; it++) {
        __syncthreads();
#pragma unroll
        for (int j = 0; j < 4; j++) {
            int e = t + j * 256, row = e >> 3, kq = e & 7;
            unsigned short h0, l0, h1, l1, h2, l2, h3, l3;
            bsplit(a_st[j].x, h0, l0); bsplit(a_st[j].y, h1, l1);
            bsplit(a_st[j].z, h2, l2); bsplit(a_st[j].w, h3, l3);
            Ah[row * PADK + kq * 2]     = pack2(h0, h1);
            Ah[row * PADK + kq * 2 + 1] = pack2(h2, h3);
            Al[row * PADK + kq * 2]     = pack2(l0, l1);
            Al[row * PADK + kq * 2 + 1] = pack2(l2, l3);
        }
#pragma unroll
        for (int j = 0; j < 8; j++) {
            int wd = t + j * 256, n = wd >> 4, kw = wd & 15;
            Bh[n * PADK + kw] = bh_st[j];
            Bl[n * PADK + kw] = bl_st[j];
        }
        __syncthreads();
        if (it < T_ / 32 - 1) {
            int k0 = (it + 1) * 32;
#pragma unroll
            for (int j = 0; j < 4; j++) {
                int e = t + j * 256, row = e >> 3, kq = e & 7;
                a_st[j] = *(const float4*)(X + (size_t)(m0 + row) * T_ + k0 + kq * 4);
            }
#pragma unroll
            for (int j = 0; j < 8; j++) {
                int wd = t + j * 256, n = wd >> 4, kw = wd & 15;
                bh_st[j] = g_WpT_h[(size_t)(n0 + n) * (T_ / 2) + k0 / 2 + kw];
                bl_st[j] = g_WpT_l[(size_t)(n0 + n) * (T_ / 2) + k0 / 2 + kw];
            }
        }
#pragma unroll
        for (int ks = 0; ks < 2; ks++) {
            unsigned ah[4][4], al[4][4], bhf[4][2], blf[4][2];
#pragma unroll
            for (int mt = 0; mt < 4; mt++) {
                int r = wm * 64 + mt * 16;
                int o = ks * 8 + t4;
                ah[mt][0] = Ah[(r + g) * PADK + o];
                ah[mt][1] = Ah[(r + g + 8) * PADK + o];
                ah[mt][2] = Ah[(r + g) * PADK + o + 4];
                ah[mt][3] = Ah[(r + g + 8) * PADK + o + 4];
                al[mt][0] = Al[(r + g) * PADK + o];
                al[mt][1] = Al[(r + g + 8) * PADK + o];
                al[mt][2] = Al[(r + g) * PADK + o + 4];
                al[mt][3] = Al[(r + g + 8) * PADK + o + 4];
            }
#pragma unroll
            for (int nt = 0; nt < 4; nt++) {
                int nr = wn * 32 + nt * 8;
                int o = ks * 8 + t4;
                bhf[nt][0] = Bh[(nr + g) * PADK + o];
                bhf[nt][1] = Bh[(nr + g) * PADK + o + 4];
                blf[nt][0] = Bl[(nr + g) * PADK + o];
                blf[nt][1] = Bl[(nr + g) * PADK + o + 4];
            }
#pragma unroll
            for (int mt = 0; mt < 4; mt++)
#pragma unroll
                for (int nt = 0; nt < 4; nt++) {
                    mma16816(acc[mt][nt], ah[mt], bhf[nt]);
                    mma16816(acc[mt][nt], ah[mt], blf[nt]);
                    mma16816(acc[mt][nt], al[mt], bhf[nt]);
                }
        }
    }

    // epilogue: +bias, split to bf16 hi/lo, store packed pairs
#pragma unroll
    for (int mt = 0; mt < 4; mt++)
#pragma unroll
        for (int nt = 0; nt < 4; nt++) {
            int m = m0 + wm * 64 + mt * 16;
            int n = n0 + wn * 32 + nt * 8 + 2 * t4;
            float b0 = bp[n], b1 = bp[n + 1];
            float c0 = acc[mt][nt][0] + b0, c1 = acc[mt][nt][1] + b1;
            float c2 = acc[mt][nt][2] + b0, c3 = acc[mt][nt][3] + b1;
            unsigned short h0, l0, h1, l1;
            bsplit(c0, h0, l0); bsplit(c1, h1, l1);
            g_Xph[(size_t)(m + g) * 128 + n / 2] = pack2(h0, h1);
            g_Xpl[(size_t)(m + g) * 128 + n / 2] = pack2(l0, l1);
            bsplit(c2, h0, l0); bsplit(c3, h1, l1);
            g_Xph[(size_t)(m + g + 8) * 128 + n / 2] = pack2(h0, h1);
            g_Xpl[(size_t)(m + g + 8) * 128 + n / 2] = pack2(l0, l1);
        }
}

// ---------------- K2: QKVS = Xp @ Wcat + bias (bf16x3 tensor-core) ----------
// M=65536, K=256, N=2048. Grid (512, 16). Scatter epilogue to g_Q/K/V/SK.
__global__ __launch_bounds__(256) void k_gemm2(
    const float* __restrict__ bq, const float* __restrict__ bk,
    const float* __restrict__ bv, const float* __restrict__ bs) {
    __shared__ unsigned Ah[128 * PADK], Al[128 * PADK];
    __shared__ unsigned Bh[128 * PADK], Bl[128 * PADK];

    const int m0 = blockIdx.x * 128, n0 = blockIdx.y * 128;
    const int t = threadIdx.x, lane = t & 31, w = t >> 5;
    const int wm = w >> 2, wn = w & 3;
    const int g = lane >> 2, t4 = lane & 3;

    float acc[4][4][4];
#pragma unroll
    for (int i = 0; i < 4; i++)
#pragma unroll
        for (int j = 0; j < 4; j++)
#pragma unroll
            for (int q = 0; q < 4; q++) acc[i][j][q] = 0.f;

    unsigned ah_st[8], al_st[8], bh_st[8], bl_st[8];
#pragma unroll
    for (int j = 0; j < 8; j++) {
        int wd = t + j * 256, row = wd >> 4, kw = wd & 15;
        ah_st[j] = g_Xph[(size_t)(m0 + row) * 128 + kw];
        al_st[j] = g_Xpl[(size_t)(m0 + row) * 128 + kw];
        bh_st[j] = g_WcT_h[(size_t)(n0 + row) * 128 + kw];
        bl_st[j] = g_WcT_l[(size_t)(n0 + row) * 128 + kw];
    }

    for (int it = 0; it < D_ / 32; it++) {
        __syncthreads();
#pragma unroll
        for (int j = 0; j < 8; j++) {
            int wd = t + j * 256, row = wd >> 4, kw = wd & 15;
            Ah[row * PADK + kw] = ah_st[j];
            Al[row * PADK + kw] = al_st[j];
            Bh[row * PADK + kw] = bh_st[j];
            Bl[row * PADK + kw] = bl_st[j];
        }
        __syncthreads();
        if (it < D_ / 32 - 1) {
            int kwb = (it + 1) * 16;
#pragma unroll
            for (int j = 0; j < 8; j++) {
                int wd = t + j * 256, row = wd >> 4, kw = wd & 15;
                ah_st[j] = g_Xph[(size_t)(m0 + row) * 128 + kwb + kw];
                al_st[j] = g_Xpl[(size_t)(m0 + row) * 128 + kwb + kw];
                bh_st[j] = g_WcT_h[(size_t)(n0 + row) * 128 + kwb + kw];
                bl_st[j] = g_WcT_l[(size_t)(n0 + row) * 128 + kwb + kw];
            }
        }
#pragma unroll
        for (int ks = 0; ks < 2; ks++) {
            unsigned ah[4][4], al[4][4], bhf[4][2], blf[4][2];
#pragma unroll
            for (int mt = 0; mt < 4; mt++) {
                int r = wm * 64 + mt * 16;
                int o = ks * 8 + t4;
                ah[mt][0] = Ah[(r + g) * PADK + o];
                ah[mt][1] = Ah[(r + g + 8) * PADK + o];
                ah[mt][2] = Ah[(r + g) * PADK + o + 4];
                ah[mt][3] = Ah[(r + g + 8) * PADK + o + 4];
                al[mt][0] = Al[(r + g) * PADK + o];
                al[mt][1] = Al[(r + g + 8) * PADK + o];
                al[mt][2] = Al[(r + g) * PADK + o + 4];
                al[mt][3] = Al[(r + g + 8) * PADK + o + 4];
            }
#pragma unroll
            for (int nt = 0; nt < 4; nt++) {
                int nr = wn * 32 + nt * 8;
                int o = ks * 8 + t4;
                bhf[nt][0] = Bh[(nr + g) * PADK + o];
                bhf[nt][1] = Bh[(nr + g) * PADK + o + 4];
                blf[nt][0] = Bl[(nr + g) * PADK + o];
                blf[nt][1] = Bl[(nr + g) * PADK + o + 4];
            }
#pragma unroll
            for (int mt = 0; mt < 4; mt++)
#pragma unroll
                for (int nt = 0; nt < 4; nt++) {
                    mma16816(acc[mt][nt], ah[mt], bhf[nt]);
                    mma16816(acc[mt][nt], ah[mt], blf[nt]);
                    mma16816(acc[mt][nt], al[mt], bhf[nt]);
                }
        }
    }

    // epilogue: bias + scatter to per-(b,h) 64x64 tiles (fp32)
#pragma unroll
    for (int nt = 0; nt < 4; nt++) {
        int cg = n0 + wn * 32 + nt * 8 + 2 * t4;
        int proj = cg >> 9, wc = cg & 511, hh = wc >> 6, c = wc & 63;
        const float* bias = (proj == 0) ? bq : (proj == 1) ? bk
                          : (proj == 2) ? bv : bs;
        float* Dst = (proj == 0) ? g_Q : (proj == 1) ? g_K
                   : (proj == 2) ? g_V : g_SK;
        float b0 = bias[wc], b1 = bias[wc + 1];
#pragma unroll
        for (int mt = 0; mt < 4; mt++) {
            int m = m0 + wm * 64 + mt * 16;
            int mA = m + g, mB = m + g + 8;
            int bA = mA >> 6, nA = mA & 63;
            int bB = mB >> 6, nB = mB & 63;
            float2 vA = make_float2(acc[mt][nt][0] + b0, acc[mt][nt][1] + b1);
            float2 vB = make_float2(acc[mt][nt][2] + b0, acc[mt][nt][3] + b1);
            *(float2*)(Dst + (((size_t)(bA * H_ + hh)) * N_ + nA) * C_ + c) = vA;
            *(float2*)(Dst + (((size_t)(bB * H_ + hh)) * N_ + nB) * C_ + c) = vB;
        }
    }
}

// ---------------- K3: attention per (b,h) -----------------------------------
__global__ __launch_bounds__(256) void k_attn2() {
    extern __shared__ float sm[];
    float* qs = sm;            // q tile (later node_out)
    float* kv = sm + 4096;     // k tile, then v tile
    float* Ss = sm + 8192;     // scores -> weights

    const int hb = blockIdx.x;
    const int b  = hb >> 3;
    const int h  = hb & 7;
    const size_t base = (size_t)hb * (N_ * C_);
    const int t = threadIdx.x;

    for (int f = t; f < 1024; f += 256) {
        ((float4*)qs)[f] = ((const float4*)(g_Q + base))[f];
        ((float4*)kv)[f] = ((const float4*)(g_K + base))[f];
    }
    __syncthreads();

    const int i  = t >> 2;
    const int g4 = t & 3;

    {
        const int j0 = g4 << 4;
        float acc[16];
#pragma unroll
        for (int jj = 0; jj < 16; jj++) acc[jj] = 0.f;
#pragma unroll
        for (int c4 = 0; c4 < 16; c4++) {
            float4 q = *(float4*)(qs + i * 64 + c4 * 4);
#pragma unroll
            for (int jj = 0; jj < 16; jj++) {
                float4 k4 = *(float4*)(kv + (j0 + jj) * 64 + c4 * 4);
                acc[jj] += q.x * k4.x + q.y * k4.y + q.z * k4.z + q.w * k4.w;
            }
        }
#pragma unroll
        for (int jj = 0; jj < 16; jj++)
            Ss[i * 64 + j0 + jj] = acc[jj] * 0.125f;
    }
    __syncthreads();

    for (int f = t; f < 1024; f += 256)
        ((float4*)kv)[f] = ((const float4*)(g_V + base))[f];

    {
        const int w = t >> 5, l = t & 31;
        for (int rr = 0; rr < 8; rr++) {
            int r = w * 8 + rr;
            float s1 = Ss[r * 64 + l], s2 = Ss[r * 64 + l + 32];
            int   c1 = g_cnt[r * 64 + l], c2 = g_cnt[r * 64 + l + 32];
            float v1 = c1 ? s1 : -1e30f;
            float v2 = c2 ? s2 : -1e30f;
            float m = fmaxf(v1, v2);
#pragma unroll
            for (int o = 16; o; o >>= 1)
                m = fmaxf(m, __shfl_xor_sync(0xffffffffu, m, o));
            if (m < -1e29f) m = 0.f;
            float a1 = c1 ? (float)c1 * __expf(s1 - m) : 0.f;
            float a2 = c2 ? (float)c2 * __expf(s2 - m) : 0.f;
            float su = a1 + a2;
#pragma unroll
            for (int o = 16; o; o >>= 1)
                su += __shfl_xor_sync(0xffffffffu, su, o);
            float inv = 1.f / (su + 1e-16f);
            Ss[r * 64 + l]      = a1 * inv;
            Ss[r * 64 + l + 32] = a2 * inv;
        }
    }
    __syncthreads();

    {
        const int c0 = g4 << 4;
        float a16[16];
#pragma unroll
        for (int jj = 0; jj < 16; jj++) a16[jj] = 0.f;
        for (int j = 0; j < 64; j++) {
            float wgt = Ss[i * 64 + j];
#pragma unroll
            for (int cc = 0; cc < 4; cc++) {
                float4 v4 = *(float4*)(kv + j * 64 + c0 + cc * 4);
                a16[cc * 4 + 0] += wgt * v4.x;
                a16[cc * 4 + 1] += wgt * v4.y;
                a16[cc * 4 + 2] += wgt * v4.z;
                a16[cc * 4 + 3] += wgt * v4.w;
            }
        }
        const float* skp = g_SK + base + i * 64 + c0;
#pragma unroll
        for (int cc = 0; cc < 4; cc++) {
            float4 s4 = *(const float4*)(skp + cc * 4);
            *(float4*)(qs + i * 64 + c0 + cc * 4) = make_float4(
                a16[cc * 4 + 0] + s4.x, a16[cc * 4 + 1] + s4.y,
                a16[cc * 4 + 2] + s4.z, a16[cc * 4 + 3] + s4.w);
        }
    }
    __syncthreads();

    {
        const int c = t & 63, ig = t >> 6;
        float s = 0.f;
#pragma unroll
        for (int r = 0; r < 16; r++) s += qs[(ig * 16 + r) * 64 + c];
        Ss[ig * 64 + c] = s;
        __syncthreads();
        if (t < 64) {
            float tot = Ss[t] + Ss[64 + t] + Ss[128 + t] + Ss[192 + t];
            g_G[(size_t)b * HC_ + h * C_ + t] = tot * (1.f / 64.f);
        }
    }
}

// ---------------- K4: out = G @ Wr + br -------------------------------------
__global__ __launch_bounds__(192) void k_out(const float* __restrict__ Wr,
                                             const float* __restrict__ br,
                                             float* __restrict__ out) {
    int b = blockIdx.x;
    int o = threadIdx.x >> 5;
    int l = threadIdx.x & 31;
    float s = 0.f;
    for (int c = l; c < HC_; c += 32)
        s += g_G[(size_t)b * HC_ + c] * Wr[c * OUT_ + o];
#pragma unroll
    for (int off = 16; off; off >>= 1)
        s += __shfl_xor_sync(0xffffffffu, s, off);
    if (l == 0) out[b * OUT_ + o] = s + br[o];
}

// ---------------------------------------------------------------------------
extern "C" void kernel_launch(void* const* d_in, const int* in_sizes, int n_in,
                              void* d_out, int out_size) {
    const float* X  = (const float*)d_in[0];
    const int*   ei = (const int*)d_in[1];
    const float* Wp = (const float*)d_in[2];
    const float* bp = (const float*)d_in[3];
    const float* Wq = (const float*)d_in[4];
    const float* bq = (const float*)d_in[5];
    const float* Wk = (const float*)d_in[6];
    const float* bk = (const float*)d_in[7];
    const float* Wv = (const float*)d_in[8];
    const float* bv = (const float*)d_in[9];
    const float* Ws = (const float*)d_in[10];
    const float* bs = (const float*)d_in[11];
    const float* Wr = (const float*)d_in[12];
    const float* br = (const float*)d_in[13];
    float* out = (float*)d_out;

    k_cnt<<<1, 1024>>>(ei);
    k_prep_wp<<<1024, 256>>>(Wp);
    k_prep_wc<<<1024, 256>>>(Wq, Wk, Wv, Ws);
    k_gemm1<<<dim3(M_ / 128, 2), 256>>>(X, bp);
    k_gemm2<<<dim3(M_ / 128, 16), 256>>>(bq, bk, bv, bs);
    k_attn2<<<B_ * H_, 256, 49152>>>();
    k_out<<<B_, 192>>>(Wr, br, out);
}

// round 8
// speedup vs baseline: 3.0834x; 1.7455x over previous
#include <cuda_runtime.h>
#include <cuda_bf16.h>

// Problem dims
#define B_   1024
#define N_   64
#define T_   2048
#define D_   256
#define H_   8
#define C_   64
#define HC_  512
#define E_   1024
#define OUT_ 6
#define M_   (B_ * N_)

#define PADK 20            // uint words per smem row: 16 data + 4 pad
#define SBUF (128 * PADK)  // words per buffer per array
#define GSMEM (8 * SBUF * 4)  // 81920 B dynamic smem for gemm kernels

// ---------------- device scratch (no allocations allowed) -------------------
__device__ unsigned g_WpT_h[D_ * (T_ / 2)];        // Wp^T split, packed pairs
__device__ unsigned g_WpT_l[D_ * (T_ / 2)];
__device__ unsigned g_WcT_h[(3 * HC_) * (D_ / 2)]; // [Wq|Wk|Wv]^T split
__device__ unsigned g_WcT_l[(3 * HC_) * (D_ / 2)];
__device__ unsigned g_Xph[(size_t)M_ * (D_ / 2)];  // Xp split bf16 pairs
__device__ unsigned g_Xpl[(size_t)M_ * (D_ / 2)];
__device__ float g_Q [(size_t)B_ * H_ * N_ * C_];
__device__ float g_K [(size_t)B_ * H_ * N_ * C_];
__device__ float g_V [(size_t)B_ * H_ * N_ * C_];
__device__ float g_G [(size_t)B_ * HC_];           // mean(agg) per (b,h)
__device__ float g_Xm[(size_t)B_ * D_];            // mean_n Xp
__device__ float g_SM[(size_t)B_ * HC_];           // mean_n skip
__device__ int   g_cnt[N_ * N_];

// ---------------- helpers ---------------------------------------------------
__device__ __forceinline__ void bsplit(float v, unsigned short& h, unsigned short& l) {
    __nv_bfloat16 bh = __float2bfloat16(v);
    float r = v - __bfloat162float(bh);
    __nv_bfloat16 bl = __float2bfloat16(r);
    h = __bfloat16_as_ushort(bh);
    l = __bfloat16_as_ushort(bl);
}
__device__ __forceinline__ unsigned pack2(unsigned short a, unsigned short b) {
    return (unsigned)a | ((unsigned)b << 16);
}
__device__ __forceinline__ float up_lo(unsigned w) {
    return __bfloat162float(__ushort_as_bfloat16((unsigned short)(w & 0xFFFF)));
}
__device__ __forceinline__ float up_hi(unsigned w) {
    return __bfloat162float(__ushort_as_bfloat16((unsigned short)(w >> 16)));
}
__device__ __forceinline__ void mma16816(float* c, const unsigned* a, const unsigned* b) {
    asm volatile(
        "mma.sync.aligned.m16n8k16.row.col.f32.bf16.bf16.f32 "
        "{%0,%1,%2,%3}, {%4,%5,%6,%7}, {%8,%9}, {%0,%1,%2,%3};"
        : "+f"(c[0]), "+f"(c[1]), "+f"(c[2]), "+f"(c[3])
        : "r"(a[0]), "r"(a[1]), "r"(a[2]), "r"(a[3]), "r"(b[0]), "r"(b[1]));
}

// Shared mainloop compute for one 32-deep K slab (bf16x3 split).
__device__ __forceinline__ void mma_slab(const unsigned* Ah, const unsigned* Al,
                                         const unsigned* Bh, const unsigned* Bl,
                                         int wm, int wn, int g, int t4,
                                         float acc[4][4][4]) {
#pragma unroll
    for (int ks = 0; ks < 2; ks++) {
        unsigned ah[4][4], al[4][4], bhf[4][2], blf[4][2];
        const int o = ks * 8 + t4;
#pragma unroll
        for (int mt = 0; mt < 4; mt++) {
            int r = wm * 64 + mt * 16;
            ah[mt][0] = Ah[(r + g) * PADK + o];
            ah[mt][1] = Ah[(r + g + 8) * PADK + o];
            ah[mt][2] = Ah[(r + g) * PADK + o + 4];
            ah[mt][3] = Ah[(r + g + 8) * PADK + o + 4];
            al[mt][0] = Al[(r + g) * PADK + o];
            al[mt][1] = Al[(r + g + 8) * PADK + o];
            al[mt][2] = Al[(r + g) * PADK + o + 4];
            al[mt][3] = Al[(r + g + 8) * PADK + o + 4];
        }
#pragma unroll
        for (int nt = 0; nt < 4; nt++) {
            int nr = wn * 32 + nt * 8;
            bhf[nt][0] = Bh[(nr + g) * PADK + o];
            bhf[nt][1] = Bh[(nr + g) * PADK + o + 4];
            blf[nt][0] = Bl[(nr + g) * PADK + o];
            blf[nt][1] = Bl[(nr + g) * PADK + o + 4];
        }
#pragma unroll
        for (int mt = 0; mt < 4; mt++)
#pragma unroll
            for (int nt = 0; nt < 4; nt++) {
                mma16816(acc[mt][nt], ah[mt], bhf[nt]);
                mma16816(acc[mt][nt], ah[mt], blf[nt]);
                mma16816(acc[mt][nt], al[mt], bhf[nt]);
            }
    }
}

// ---------------- K0: edge-count matrix (dtype-robust) ----------------------
__global__ void k_cnt(const int* __restrict__ ei) {
    __shared__ int odd_nz;
    int t = threadIdx.x;  // 1024 = E_
    if (t == 0) odd_nz = 0;
    for (int i = t; i < N_ * N_; i += blockDim.x) g_cnt[i] = 0;
    __syncthreads();
    if (ei[2 * t + 1] != 0) atomicOr(&odd_nz, 1);
    __syncthreads();
    int s, d;
    if (odd_nz) { s = ei[t] & 63; d = ei[E_ + t] & 63; }
    else        { s = ei[2 * t] & 63; d = ei[2 * (E_ + t)] & 63; }
    atomicAdd(&g_cnt[d * N_ + s], 1);
}

// ---------------- prep: split + transpose weights ---------------------------
__global__ __launch_bounds__(256) void k_prep_wp(const float* __restrict__ Wp) {
    int idx = blockIdx.x * 256 + threadIdx.x;     // 256*1024
    int n = idx >> 10, kw = idx & 1023, k = kw * 2;
    float v0 = Wp[(size_t)k * D_ + n];
    float v1 = Wp[(size_t)(k + 1) * D_ + n];
    unsigned short h0, l0, h1, l1;
    bsplit(v0, h0, l0); bsplit(v1, h1, l1);
    g_WpT_h[idx] = pack2(h0, h1);
    g_WpT_l[idx] = pack2(l0, l1);
}
__global__ __launch_bounds__(256) void k_prep_wc(
    const float* __restrict__ Wq, const float* __restrict__ Wk,
    const float* __restrict__ Wv) {
    int idx = blockIdx.x * 256 + threadIdx.x;     // 1536*128
    int col = idx >> 7, kw = idx & 127, k = kw * 2;
    int proj = col >> 9, wc = col & 511;
    const float* W = (proj == 0) ? Wq : (proj == 1) ? Wk : Wv;
    float v0 = W[(size_t)k * HC_ + wc];
    float v1 = W[(size_t)(k + 1) * HC_ + wc];
    unsigned short h0, l0, h1, l1;
    bsplit(v0, h0, l0); bsplit(v1, h1, l1);
    g_WcT_h[idx] = pack2(h0, h1);
    g_WcT_l[idx] = pack2(l0, l1);
}

// ---------------- K1: Xp = X @ Wp + bp  (bf16x3, double-buffered) -----------
__global__ __launch_bounds__(256) void k_gemm1(const float* __restrict__ X,
                                               const float* __restrict__ bp) {
    extern __shared__ unsigned smg[];
    unsigned* Ah = smg;
    unsigned* Al = smg + 2 * SBUF;
    unsigned* Bh = smg + 4 * SBUF;
    unsigned* Bl = smg + 6 * SBUF;

    const int m0 = blockIdx.x * 128, n0 = blockIdx.y * 128;
    const int t = threadIdx.x, lane = t & 31, w = t >> 5;
    const int wm = w >> 2, wn = w & 3;
    const int g = lane >> 2, t4 = lane & 3;

    float acc[4][4][4];
#pragma unroll
    for (int i = 0; i < 4; i++)
#pragma unroll
        for (int j = 0; j < 4; j++)
#pragma unroll
            for (int q = 0; q < 4; q++) acc[i][j][q] = 0.f;

    float4 a_st[4];
    unsigned bh_st[8], bl_st[8];

    auto gloadA = [&](int it) {
        int k0 = it * 32;
#pragma unroll
        for (int j = 0; j < 4; j++) {
            int e = t + j * 256, row = e >> 3, kq = e & 7;
            a_st[j] = *(const float4*)(X + (size_t)(m0 + row) * T_ + k0 + kq * 4);
        }
    };
    auto gloadB = [&](int it) {
        int kwb = it * 16;
#pragma unroll
        for (int j = 0; j < 8; j++) {
            int wd = t + j * 256, n = wd >> 4, kw = wd & 15;
            bh_st[j] = g_WpT_h[(size_t)(n0 + n) * (T_ / 2) + kwb + kw];
            bl_st[j] = g_WpT_l[(size_t)(n0 + n) * (T_ / 2) + kwb + kw];
        }
    };
    auto stAB = [&](int p) {
        unsigned* ah = Ah + p * SBUF; unsigned* al = Al + p * SBUF;
        unsigned* bh = Bh + p * SBUF; unsigned* bl = Bl + p * SBUF;
#pragma unroll
        for (int j = 0; j < 4; j++) {
            int e = t + j * 256, row = e >> 3, kq = e & 7;
            unsigned short h0, l0, h1, l1, h2, l2, h3, l3;
            bsplit(a_st[j].x, h0, l0); bsplit(a_st[j].y, h1, l1);
            bsplit(a_st[j].z, h2, l2); bsplit(a_st[j].w, h3, l3);
            ah[row * PADK + kq * 2]     = pack2(h0, h1);
            ah[row * PADK + kq * 2 + 1] = pack2(h2, h3);
            al[row * PADK + kq * 2]     = pack2(l0, l1);
            al[row * PADK + kq * 2 + 1] = pack2(l2, l3);
        }
#pragma unroll
        for (int j = 0; j < 8; j++) {
            int wd = t + j * 256, n = wd >> 4, kw = wd & 15;
            bh[n * PADK + kw] = bh_st[j];
            bl[n * PADK + kw] = bl_st[j];
        }
    };

    const int NIT = T_ / 32;
    gloadA(0); gloadB(0);
    stAB(0);
    gloadA(1); gloadB(1);
    __syncthreads();
    for (int it = 0; it < NIT; it++) {
        int cur = it & 1;
        if (it + 1 < NIT) stAB(cur ^ 1);
        if (it + 2 < NIT) { gloadA(it + 2); gloadB(it + 2); }
        mma_slab(Ah + cur * SBUF, Al + cur * SBUF,
                 Bh + cur * SBUF, Bl + cur * SBUF, wm, wn, g, t4, acc);
        __syncthreads();
    }

    // epilogue: +bias, split to bf16 hi/lo, store packed pairs
#pragma unroll
    for (int mt = 0; mt < 4; mt++)
#pragma unroll
        for (int nt = 0; nt < 4; nt++) {
            int m = m0 + wm * 64 + mt * 16;
            int n = n0 + wn * 32 + nt * 8 + 2 * t4;
            float b0 = bp[n], b1 = bp[n + 1];
            float c0 = acc[mt][nt][0] + b0, c1 = acc[mt][nt][1] + b1;
            float c2 = acc[mt][nt][2] + b0, c3 = acc[mt][nt][3] + b1;
            unsigned short h0, l0, h1, l1;
            bsplit(c0, h0, l0); bsplit(c1, h1, l1);
            g_Xph[(size_t)(m + g) * 128 + n / 2] = pack2(h0, h1);
            g_Xpl[(size_t)(m + g) * 128 + n / 2] = pack2(l0, l1);
            bsplit(c2, h0, l0); bsplit(c3, h1, l1);
            g_Xph[(size_t)(m + g + 8) * 128 + n / 2] = pack2(h0, h1);
            g_Xpl[(size_t)(m + g + 8) * 128 + n / 2] = pack2(l0, l1);
        }
}

// ---------------- K2: QKV = Xp @ [Wq|Wk|Wv] + bias (double-buffered) --------
__global__ __launch_bounds__(256) void k_gemm2(
    const float* __restrict__ bq, const float* __restrict__ bk,
    const float* __restrict__ bv) {
    extern __shared__ unsigned smg[];
    unsigned* Ah = smg;
    unsigned* Al = smg + 2 * SBUF;
    unsigned* Bh = smg + 4 * SBUF;
    unsigned* Bl = smg + 6 * SBUF;

    const int m0 = blockIdx.x * 128, n0 = blockIdx.y * 128;
    const int t = threadIdx.x, lane = t & 31, w = t >> 5;
    const int wm = w >> 2, wn = w & 3;
    const int g = lane >> 2, t4 = lane & 3;

    float acc[4][4][4];
#pragma unroll
    for (int i = 0; i < 4; i++)
#pragma unroll
        for (int j = 0; j < 4; j++)
#pragma unroll
            for (int q = 0; q < 4; q++) acc[i][j][q] = 0.f;

    unsigned ah_st[8], al_st[8], bh_st[8], bl_st[8];

    auto gload = [&](int it) {
        int kwb = it * 16;
#pragma unroll
        for (int j = 0; j < 8; j++) {
            int wd = t + j * 256, row = wd >> 4, kw = wd & 15;
            ah_st[j] = g_Xph[(size_t)(m0 + row) * 128 + kwb + kw];
            al_st[j] = g_Xpl[(size_t)(m0 + row) * 128 + kwb + kw];
            bh_st[j] = g_WcT_h[(size_t)(n0 + row) * 128 + kwb + kw];
            bl_st[j] = g_WcT_l[(size_t)(n0 + row) * 128 + kwb + kw];
        }
    };
    auto stAB = [&](int p) {
        unsigned* ah = Ah + p * SBUF; unsigned* al = Al + p * SBUF;
        unsigned* bh = Bh + p * SBUF; unsigned* bl = Bl + p * SBUF;
#pragma unroll
        for (int j = 0; j < 8; j++) {
            int wd = t + j * 256, row = wd >> 4, kw = wd & 15;
            ah[row * PADK + kw] = ah_st[j];
            al[row * PADK + kw] = al_st[j];
            bh[row * PADK + kw] = bh_st[j];
            bl[row * PADK + kw] = bl_st[j];
        }
    };

    const int NIT = D_ / 32;  // 8
    gload(0);
    stAB(0);
    gload(1);
    __syncthreads();
    for (int it = 0; it < NIT; it++) {
        int cur = it & 1;
        if (it + 1 < NIT) stAB(cur ^ 1);
        if (it + 2 < NIT) gload(it + 2);
        mma_slab(Ah + cur * SBUF, Al + cur * SBUF,
                 Bh + cur * SBUF, Bl + cur * SBUF, wm, wn, g, t4, acc);
        __syncthreads();
    }

    // epilogue: bias + scatter to per-(b,h) 64x64 tiles (fp32)
#pragma unroll
    for (int nt = 0; nt < 4; nt++) {
        int cg = n0 + wn * 32 + nt * 8 + 2 * t4;
        int proj = cg >> 9, wc = cg & 511, hh = wc >> 6, c = wc & 63;
        const float* bias = (proj == 0) ? bq : (proj == 1) ? bk : bv;
        float* Dst = (proj == 0) ? g_Q : (proj == 1) ? g_K : g_V;
        float b0 = bias[wc], b1 = bias[wc + 1];
#pragma unroll
        for (int mt = 0; mt < 4; mt++) {
            int m = m0 + wm * 64 + mt * 16;
            int mA = m + g, mB = m + g + 8;
            int bA = mA >> 6, nA = mA & 63;
            int bB = mB >> 6, nB = mB & 63;
            float2 vA = make_float2(acc[mt][nt][0] + b0, acc[mt][nt][1] + b1);
            float2 vB = make_float2(acc[mt][nt][2] + b0, acc[mt][nt][3] + b1);
            *(float2*)(Dst + (((size_t)(bA * H_ + hh)) * N_ + nA) * C_ + c) = vA;
            *(float2*)(Dst + (((size_t)(bB * H_ + hh)) * N_ + nB) * C_ + c) = vB;
        }
    }
}

// ---------------- skip-mean path --------------------------------------------
// g_Xm[b] = mean_n Xp[b]  (reconstruct fp32 from split bf16)
__global__ __launch_bounds__(128) void k_xmean() {
    int b = blockIdx.x, t = threadIdx.x;  // t = word 0..127
    float s0 = 0.f, s1 = 0.f;
    for (int n = 0; n < 64; n++) {
        unsigned wh = g_Xph[(size_t)(b * 64 + n) * 128 + t];
        unsigned wl = g_Xpl[(size_t)(b * 64 + n) * 128 + t];
        s0 += up_lo(wh) + up_lo(wl);
        s1 += up_hi(wh) + up_hi(wl);
    }
    g_Xm[b * D_ + 2 * t]     = s0 * (1.f / 64.f);
    g_Xm[b * D_ + 2 * t + 1] = s1 * (1.f / 64.f);
}
// g_SM[b] = g_Xm[b] @ Ws + bs  (4 batches per block to amortize Ws reads)
__global__ __launch_bounds__(256) void k_skip(const float* __restrict__ Ws,
                                              const float* __restrict__ bs) {
    __shared__ float xm[4][256];
    int b0 = blockIdx.x * 4, t = threadIdx.x;
#pragma unroll
    for (int q = 0; q < 4; q++) xm[q][t] = g_Xm[(size_t)(b0 + q) * D_ + t];
    __syncthreads();
    float a0[4], a1[4];
    float bs0 = bs[t], bs1 = bs[t + 256];
#pragma unroll
    for (int q = 0; q < 4; q++) { a0[q] = bs0; a1[q] = bs1; }
    for (int k = 0; k < 256; k++) {
        float w0 = Ws[(size_t)k * HC_ + t];
        float w1 = Ws[(size_t)k * HC_ + t + 256];
#pragma unroll
        for (int q = 0; q < 4; q++) {
            a0[q] += xm[q][k] * w0;
            a1[q] += xm[q][k] * w1;
        }
    }
#pragma unroll
    for (int q = 0; q < 4; q++) {
        g_SM[(size_t)(b0 + q) * HC_ + t]       = a0[q];
        g_SM[(size_t)(b0 + q) * HC_ + t + 256] = a1[q];
    }
}

// ---------------- K3: attention per (b,h) -----------------------------------
// scores = qk^T/8 (4x4 reg-blocked, swizzled K), count-weighted softmax,
// then mean_n(agg) = (colmean of w_hat) . V   (matvec -- AV GEMM eliminated).
__global__ __launch_bounds__(256) void k_attn3() {
    __shared__ float qs[4096];   // q, then v
    __shared__ float ks[4096];   // k (swizzled), then [0:64) wbar, [64:128) out
    __shared__ float Ss[4096];   // scores -> normalized weights

    const int hb = blockIdx.x, b = hb >> 3, h = hb & 7;
    const size_t base = (size_t)hb * (N_ * C_);
    const int t = threadIdx.x;

    // load q (linear) and k (XOR-swizzled rows: word c4 -> c4 ^ (row>>2))
    for (int f = t; f < 1024; f += 256) {
        ((float4*)qs)[f] = ((const float4*)(g_Q + base))[f];
        int row = f >> 4, c4 = f & 15;
        *(float4*)(ks + row * 64 + ((c4 ^ (row >> 2)) & 15) * 4) =
            ((const float4*)(g_K + base))[f];
    }
    __syncthreads();

    // ---- scores: 4x4 register blocking; 256 thr = 16 row-blk x 16 col-blk --
    {
        const int ti = t >> 4, tj = t & 15;
        float acc[4][4];
#pragma unroll
        for (int r = 0; r < 4; r++)
#pragma unroll
            for (int j = 0; j < 4; j++) acc[r][j] = 0.f;
#pragma unroll
        for (int c4 = 0; c4 < 16; c4++) {
            float4 q4[4], k4[4];
#pragma unroll
            for (int r = 0; r < 4; r++)
                q4[r] = *(float4*)(qs + (ti * 4 + r) * 64 + c4 * 4);
#pragma unroll
            for (int j = 0; j < 4; j++)
                k4[j] = *(float4*)(ks + (tj * 4 + j) * 64 + ((c4 ^ tj) & 15) * 4);
#pragma unroll
            for (int r = 0; r < 4; r++)
#pragma unroll
                for (int j = 0; j < 4; j++)
                    acc[r][j] += q4[r].x * k4[j].x + q4[r].y * k4[j].y +
                                 q4[r].z * k4[j].z + q4[r].w * k4[j].w;
        }
#pragma unroll
        for (int r = 0; r < 4; r++)
            *(float4*)(Ss + (ti * 4 + r) * 64 + tj * 4) = make_float4(
                acc[r][0] * 0.125f, acc[r][1] * 0.125f,
                acc[r][2] * 0.125f, acc[r][3] * 0.125f);
    }
    __syncthreads();

    // overwrite q with v (k is dead too); zero accumulators in ks[0:128)
    for (int f = t; f < 1024; f += 256)
        ((float4*)qs)[f] = ((const float4*)(g_V + base))[f];
    if (t < 128) ks[t] = 0.f;

    // ---- count-weighted masked softmax per destination row -----------------
    {
        const int w = t >> 5, l = t & 31;
        for (int rr = 0; rr < 8; rr++) {
            int r = w * 8 + rr;
            float s1 = Ss[r * 64 + l], s2 = Ss[r * 64 + l + 32];
            int   c1 = g_cnt[r * 64 + l], c2 = g_cnt[r * 64 + l + 32];
            float v1 = c1 ? s1 : -1e30f;
            float v2 = c2 ? s2 : -1e30f;
            float m = fmaxf(v1, v2);
#pragma unroll
            for (int o = 16; o; o >>= 1)
                m = fmaxf(m, __shfl_xor_sync(0xffffffffu, m, o));
            if (m < -1e29f) m = 0.f;
            float a1 = c1 ? (float)c1 * __expf(s1 - m) : 0.f;
            float a2 = c2 ? (float)c2 * __expf(s2 - m) : 0.f;
            float su = a1 + a2;
#pragma unroll
            for (int o = 16; o; o >>= 1)
                su += __shfl_xor_sync(0xffffffffu, su, o);
            float inv = 1.f / (su + 1e-16f);
            Ss[r * 64 + l]      = a1 * inv;
            Ss[r * 64 + l + 32] = a2 * inv;
        }
    }
    __syncthreads();

    // ---- wbar[j] = sum_i w_hat[i][j]  (column sum; /64 folded at the end) --
    {
        const int c = t & 63, gq = t >> 6;
        float s = 0.f;
#pragma unroll
        for (int r = 0; r < 16; r++) s += Ss[(gq * 16 + r) * 64 + c];
        atomicAdd(&ks[c], s);
    }
    __syncthreads();

    // ---- out[c] = sum_j wbar[j] * v[j][c] ----------------------------------
    {
        const int c = t & 63, gq = t >> 6;
        float s = 0.f;
#pragma unroll
        for (int r = 0; r < 16; r++) {
            int j = gq * 16 + r;
            s += ks[j] * qs[j * 64 + c];
        }
        atomicAdd(&ks[64 + c], s);
    }
    __syncthreads();
    if (t < 64)
        g_G[(size_t)b * HC_ + h * C_ + t] = ks[64 + t] * (1.f / 64.f);
}

// ---------------- K4: out = (G + SM) @ Wr + br ------------------------------
__global__ __launch_bounds__(192) void k_out(const float* __restrict__ Wr,
                                             const float* __restrict__ br,
                                             float* __restrict__ out) {
    int b = blockIdx.x;
    int o = threadIdx.x >> 5;
    int l = threadIdx.x & 31;
    float s = 0.f;
    for (int c = l; c < HC_; c += 32)
        s += (g_G[(size_t)b * HC_ + c] + g_SM[(size_t)b * HC_ + c]) *
             Wr[c * OUT_ + o];
#pragma unroll
    for (int off = 16; off; off >>= 1)
        s += __shfl_xor_sync(0xffffffffu, s, off);
    if (l == 0) out[b * OUT_ + o] = s + br[o];
}

// ---------------------------------------------------------------------------
extern "C" void kernel_launch(void* const* d_in, const int* in_sizes, int n_in,
                              void* d_out, int out_size) {
    const float* X  = (const float*)d_in[0];
    const int*   ei = (const int*)d_in[1];
    const float* Wp = (const float*)d_in[2];
    const float* bp = (const float*)d_in[3];
    const float* Wq = (const float*)d_in[4];
    const float* bq = (const float*)d_in[5];
    const float* Wk = (const float*)d_in[6];
    const float* bk = (const float*)d_in[7];
    const float* Wv = (const float*)d_in[8];
    const float* bv = (const float*)d_in[9];
    const float* Ws = (const float*)d_in[10];
    const float* bs = (const float*)d_in[11];
    const float* Wr = (const float*)d_in[12];
    const float* br = (const float*)d_in[13];
    float* out = (float*)d_out;

    cudaFuncSetAttribute(k_gemm1, cudaFuncAttributeMaxDynamicSharedMemorySize, GSMEM);
    cudaFuncSetAttribute(k_gemm2, cudaFuncAttributeMaxDynamicSharedMemorySize, GSMEM);

    k_cnt<<<1, 1024>>>(ei);
    k_prep_wp<<<1024, 256>>>(Wp);
    k_prep_wc<<<768, 256>>>(Wq, Wk, Wv);
    k_gemm1<<<dim3(M_ / 128, 2), 256, GSMEM>>>(X, bp);
    k_xmean<<<B_, 128>>>();
    k_skip<<<B_ / 4, 256>>>(Ws, bs);
    k_gemm2<<<dim3(M_ / 128, 12), 256, GSMEM>>>(bq, bk, bv);
    k_attn3<<<B_ * H_, 256>>>();
    k_out<<<B_, 192>>>(Wr, br, out);
}

// round 13
// speedup vs baseline: 3.2977x; 1.0695x over previous
#include <cuda_runtime.h>
#include <cuda_bf16.h>
#include <cstdint>

// Problem dims
#define B_   1024
#define N_   64
#define T_   2048
#define D_   256
#define H_   8
#define C_   64
#define HC_  512
#define E_   1024
#define OUT_ 6
#define M_   (B_ * N_)

#define PADK   20                    // words per smem row (16 data + 4 pad)
#define GEMM_SMEM 61440              // Ah(10240)+Al(10240)+Bh(20480)+Bl(20480)

// ---------------- device scratch --------------------------------------------
__device__ unsigned g_WpT_h[D_ * (T_ / 2)];        // Wp^T split, packed pairs
__device__ unsigned g_WpT_l[D_ * (T_ / 2)];
__device__ unsigned g_WcT_h[(3 * HC_) * (D_ / 2)]; // [Wq|Wk|Wv]^T split
__device__ unsigned g_WcT_l[(3 * HC_) * (D_ / 2)];
__device__ unsigned g_Xph[(size_t)M_ * (D_ / 2)];  // Xp split bf16 pairs
__device__ unsigned g_Xpl[(size_t)M_ * (D_ / 2)];
__device__ float g_Q [(size_t)B_ * H_ * N_ * C_];
__device__ float g_K [(size_t)B_ * H_ * N_ * C_];
__device__ float g_V [(size_t)B_ * H_ * N_ * C_];
__device__ float g_G [(size_t)B_ * HC_];
__device__ float g_Xm[(size_t)B_ * D_];
__device__ float g_SM[(size_t)B_ * HC_];
__device__ int   g_cnt[N_ * N_];

// ---------------- helpers ---------------------------------------------------
__device__ __forceinline__ void bsplit(float v, unsigned short& h, unsigned short& l) {
    __nv_bfloat16 bh = __float2bfloat16(v);
    float r = v - __bfloat162float(bh);
    __nv_bfloat16 bl = __float2bfloat16(r);
    h = __bfloat16_as_ushort(bh);
    l = __bfloat16_as_ushort(bl);
}
__device__ __forceinline__ unsigned pack2(unsigned short a, unsigned short b) {
    return (unsigned)a | ((unsigned)b << 16);
}
__device__ __forceinline__ float up_lo(unsigned w) {
    return __bfloat162float(__ushort_as_bfloat16((unsigned short)(w & 0xFFFF)));
}
__device__ __forceinline__ float up_hi(unsigned w) {
    return __bfloat162float(__ushort_as_bfloat16((unsigned short)(w >> 16)));
}
__device__ __forceinline__ void mma16816(float* c, const uint32_t* a, const uint32_t* b) {
    asm volatile(
        "mma.sync.aligned.m16n8k16.row.col.f32.bf16.bf16.f32 "
        "{%0,%1,%2,%3}, {%4,%5,%6,%7}, {%8,%9}, {%0,%1,%2,%3};"
        : "+f"(c[0]), "+f"(c[1]), "+f"(c[2]), "+f"(c[3])
        : "r"(a[0]), "r"(a[1]), "r"(a[2]), "r"(a[3]), "r"(b[0]), "r"(b[1]));
}
__device__ __forceinline__ void ldsm4(uint32_t* r, uint32_t a) {
    asm volatile("ldmatrix.sync.aligned.m8n8.x4.shared.b16 {%0,%1,%2,%3}, [%4];"
                 : "=r"(r[0]), "=r"(r[1]), "=r"(r[2]), "=r"(r[3]) : "r"(a));
}
__device__ __forceinline__ uint32_t s2u(const void* p) {
    uint32_t a;
    asm("{ .reg .u64 t; cvta.to.shared.u64 t, %1; cvt.u32.u64 %0, t; }"
        : "=r"(a) : "l"(p));
    return a;
}

// One 32-deep K slab: ldmatrix fragments + bf16x3 HMMA.
// smem layout (bytes): Ah@0 Al@10240 Bh@20480 Bl@40960; rows of PADK words.
__device__ __forceinline__ void slab_compute(uint32_t sb, int a_row, int a_byte,
                                             int b_row, int b_byte,
                                             float acc[2][8][4]) {
#pragma unroll
    for (int ks = 0; ks < 2; ks++) {
        uint32_t ah[2][4], al[2][4];
#pragma unroll
        for (int mt = 0; mt < 2; mt++) {
            uint32_t ad = sb + (a_row + mt * 16) * 80 + ks * 32 + a_byte;
            ldsm4(ah[mt], ad);
            ldsm4(al[mt], ad + 10240);
        }
#pragma unroll
        for (int p = 0; p < 4; p++) {
            uint32_t bd = sb + 20480 + (b_row + p * 16) * 80 + ks * 32 + b_byte;
            uint32_t bh[4], bl[4];
            ldsm4(bh, bd);
            ldsm4(bl, bd + 20480);
#pragma unroll
            for (int mt = 0; mt < 2; mt++) {
                mma16816(acc[mt][2 * p],     ah[mt], bh);
                mma16816(acc[mt][2 * p],     ah[mt], bl);
                mma16816(acc[mt][2 * p],     al[mt], bh);
                mma16816(acc[mt][2 * p + 1], ah[mt], bh + 2);
                mma16816(acc[mt][2 * p + 1], ah[mt], bl + 2);
                mma16816(acc[mt][2 * p + 1], al[mt], bh + 2);
            }
        }
    }
}

// ---------------- K0: edge-count matrix (dtype-robust) ----------------------
__global__ void k_cnt(const int* __restrict__ ei) {
    __shared__ int odd_nz;
    int t = threadIdx.x;  // 1024 = E_
    if (t == 0) odd_nz = 0;
    for (int i = t; i < N_ * N_; i += blockDim.x) g_cnt[i] = 0;
    __syncthreads();
    if (ei[2 * t + 1] != 0) atomicOr(&odd_nz, 1);
    __syncthreads();
    int s, d;
    if (odd_nz) { s = ei[t] & 63; d = ei[E_ + t] & 63; }
    else        { s = ei[2 * t] & 63; d = ei[2 * (E_ + t)] & 63; }
    atomicAdd(&g_cnt[d * N_ + s], 1);
}

// ---------------- prep: split + transpose weights ---------------------------
__global__ __launch_bounds__(256) void k_prep_wp(const float* __restrict__ Wp) {
    int idx = blockIdx.x * 256 + threadIdx.x;     // 256*1024
    int n = idx >> 10, kw = idx & 1023, k = kw * 2;
    float v0 = Wp[(size_t)k * D_ + n];
    float v1 = Wp[(size_t)(k + 1) * D_ + n];
    unsigned short h0, l0, h1, l1;
    bsplit(v0, h0, l0); bsplit(v1, h1, l1);
    g_WpT_h[idx] = pack2(h0, h1);
    g_WpT_l[idx] = pack2(l0, l1);
}
__global__ __launch_bounds__(256) void k_prep_wc(
    const float* __restrict__ Wq, const float* __restrict__ Wk,
    const float* __restrict__ Wv) {
    int idx = blockIdx.x * 256 + threadIdx.x;     // 1536*128
    int col = idx >> 7, kw = idx & 127, k = kw * 2;
    int proj = col >> 9, wc = col & 511;
    const float* W = (proj == 0) ? Wq : (proj == 1) ? Wk : Wv;
    float v0 = W[(size_t)k * HC_ + wc];
    float v1 = W[(size_t)(k + 1) * HC_ + wc];
    unsigned short h0, l0, h1, l1;
    bsplit(v0, h0, l0); bsplit(v1, h1, l1);
    g_WcT_h[idx] = pack2(h0, h1);
    g_WcT_l[idx] = pack2(l0, l1);
}

// ---------------- K1: Xp = X @ Wp + bp  (512 thr, BN=256, ldmatrix) ---------
__global__ __launch_bounds__(512) void k_gemm1n(const float* __restrict__ X,
                                                const float* __restrict__ bp) {
    extern __shared__ unsigned smw[];
    const uint32_t sb = s2u(smw);
    const int t = threadIdx.x, lane = t & 31, w = t >> 5;
    const int wm = w >> 2, wn = w & 3;
    const int g = lane >> 2, t4 = lane & 3;
    const int m0 = blockIdx.x * 128;

    const int a_row  = wm * 32 + (lane & 15);
    const int a_byte = ((lane >> 4) & 1) * 16;
    const int b_row  = wn * 64 + ((lane >> 4) & 1) * 8 + (lane & 7);
    const int b_byte = ((lane >> 3) & 1) * 16;

    float acc[2][8][4];
#pragma unroll
    for (int i = 0; i < 2; i++)
#pragma unroll
        for (int j = 0; j < 8; j++)
#pragma unroll
            for (int q = 0; q < 4; q++) acc[i][j][q] = 0.f;

    const int arow_ld = t >> 2, aq = t & 3;      // A: 4 thr/row, 8 floats each
    const int brow_ld = t >> 1, bhalf = t & 1;   // B: 2 thr/row, 8 words each

    float4 a_st[2];
    uint4  b_sth[2], b_stl[2];

    auto gload = [&](int it) {
        const float* ap = X + (size_t)(m0 + arow_ld) * T_ + it * 32 + aq * 8;
        a_st[0] = *(const float4*)(ap);
        a_st[1] = *(const float4*)(ap + 4);
        const size_t bb = (size_t)brow_ld * (T_ / 2) + it * 16 + bhalf * 8;
        b_sth[0] = *(const uint4*)(g_WpT_h + bb);
        b_sth[1] = *(const uint4*)(g_WpT_h + bb + 4);
        b_stl[0] = *(const uint4*)(g_WpT_l + bb);
        b_stl[1] = *(const uint4*)(g_WpT_l + bb + 4);
    };
    auto sstore = [&]() {
        unsigned* Ah = smw;        unsigned* Al = smw + 2560;
        unsigned* Bh = smw + 5120; unsigned* Bl = smw + 10240;
#pragma unroll
        for (int i = 0; i < 2; i++) {
            unsigned short h0, l0, h1, l1, h2, l2, h3, l3;
            bsplit(a_st[i].x, h0, l0); bsplit(a_st[i].y, h1, l1);
            bsplit(a_st[i].z, h2, l2); bsplit(a_st[i].w, h3, l3);
            int wd = arow_ld * PADK + aq * 4 + i * 2;
            *(uint2*)(Ah + wd) = make_uint2(pack2(h0, h1), pack2(h2, h3));
            *(uint2*)(Al + wd) = make_uint2(pack2(l0, l1), pack2(l2, l3));
        }
        int wd = brow_ld * PADK + bhalf * 8;
        *(uint4*)(Bh + wd)     = b_sth[0];
        *(uint4*)(Bh + wd + 4) = b_sth[1];
        *(uint4*)(Bl + wd)     = b_stl[0];
        *(uint4*)(Bl + wd + 4) = b_stl[1];
    };

    const int NIT = T_ / 32;  // 64
    gload(0);
    for (int it = 0; it < NIT; it++) {
        __syncthreads();
        sstore();
        __syncthreads();
        if (it + 1 < NIT) gload(it + 1);
        slab_compute(sb, a_row, a_byte, b_row, b_byte, acc);
    }

    // epilogue: +bias, split, store packed pairs
#pragma unroll
    for (int mt = 0; mt < 2; mt++)
#pragma unroll
        for (int nt = 0; nt < 8; nt++) {
            int n = wn * 64 + nt * 8 + 2 * t4;
            float b0 = bp[n], b1 = bp[n + 1];
            int mA = m0 + wm * 32 + mt * 16 + g;
            unsigned short h0, l0, h1, l1;
            float c0 = acc[mt][nt][0] + b0, c1 = acc[mt][nt][1] + b1;
            bsplit(c0, h0, l0); bsplit(c1, h1, l1);
            g_Xph[(size_t)mA * 128 + n / 2] = pack2(h0, h1);
            g_Xpl[(size_t)mA * 128 + n / 2] = pack2(l0, l1);
            float c2 = acc[mt][nt][2] + b0, c3 = acc[mt][nt][3] + b1;
            bsplit(c2, h0, l0); bsplit(c3, h1, l1);
            g_Xph[(size_t)(mA + 8) * 128 + n / 2] = pack2(h0, h1);
            g_Xpl[(size_t)(mA + 8) * 128 + n / 2] = pack2(l0, l1);
        }
}

// ---------------- K2: QKV = Xp @ [Wq|Wk|Wv] + bias (512 thr, ldmatrix) ------
__global__ __launch_bounds__(512) void k_gemm2n(
    const float* __restrict__ bq, const float* __restrict__ bk,
    const float* __restrict__ bv) {
    extern __shared__ unsigned smw[];
    const uint32_t sb = s2u(smw);
    const int t = threadIdx.x, lane = t & 31, w = t >> 5;
    const int wm = w >> 2, wn = w & 3;
    const int g = lane >> 2, t4 = lane & 3;
    const int m0 = blockIdx.x * 128, n0 = blockIdx.y * 256;

    const int a_row  = wm * 32 + (lane & 15);
    const int a_byte = ((lane >> 4) & 1) * 16;
    const int b_row  = wn * 64 + ((lane >> 4) & 1) * 8 + (lane & 7);
    const int b_byte = ((lane >> 3) & 1) * 16;

    float acc[2][8][4];
#pragma unroll
    for (int i = 0; i < 2; i++)
#pragma unroll
        for (int j = 0; j < 8; j++)
#pragma unroll
            for (int q = 0; q < 4; q++) acc[i][j][q] = 0.f;

    const int arow_ld = t >> 2, aq = t & 3;
    const int brow_ld = t >> 1, bhalf = t & 1;

    uint4 a_sth, a_stl, b_sth[2], b_stl[2];

    auto gload = [&](int it) {
        const size_t ab = (size_t)(m0 + arow_ld) * 128 + it * 16 + aq * 4;
        a_sth = *(const uint4*)(g_Xph + ab);
        a_stl = *(const uint4*)(g_Xpl + ab);
        const size_t bb = (size_t)(n0 + brow_ld) * 128 + it * 16 + bhalf * 8;
        b_sth[0] = *(const uint4*)(g_WcT_h + bb);
        b_sth[1] = *(const uint4*)(g_WcT_h + bb + 4);
        b_stl[0] = *(const uint4*)(g_WcT_l + bb);
        b_stl[1] = *(const uint4*)(g_WcT_l + bb + 4);
    };
    auto sstore = [&]() {
        unsigned* Ah = smw;        unsigned* Al = smw + 2560;
        unsigned* Bh = smw + 5120; unsigned* Bl = smw + 10240;
        int wa = arow_ld * PADK + aq * 4;
        *(uint4*)(Ah + wa) = a_sth;
        *(uint4*)(Al + wa) = a_stl;
        int wd = brow_ld * PADK + bhalf * 8;
        *(uint4*)(Bh + wd)     = b_sth[0];
        *(uint4*)(Bh + wd + 4) = b_sth[1];
        *(uint4*)(Bl + wd)     = b_stl[0];
        *(uint4*)(Bl + wd + 4) = b_stl[1];
    };

    const int NIT = D_ / 32;  // 8
    gload(0);
    for (int it = 0; it < NIT; it++) {
        __syncthreads();
        sstore();
        __syncthreads();
        if (it + 1 < NIT) gload(it + 1);
        slab_compute(sb, a_row, a_byte, b_row, b_byte, acc);
    }

    // epilogue: bias + scatter to per-(b,h) 64x64 tiles (fp32)
#pragma unroll
    for (int nt = 0; nt < 8; nt++) {
        int cg = n0 + wn * 64 + nt * 8 + 2 * t4;
        int proj = cg >> 9, wc = cg & 511, hh = wc >> 6, c = wc & 63;
        const float* bias = (proj == 0) ? bq : (proj == 1) ? bk : bv;
        float* Dst = (proj == 0) ? g_Q : (proj == 1) ? g_K : g_V;
        float b0 = bias[wc], b1 = bias[wc + 1];
#pragma unroll
        for (int mt = 0; mt < 2; mt++) {
            int mA = m0 + wm * 32 + mt * 16 + g;
            int mB = mA + 8;
            int bA = mA >> 6, nA = mA & 63;
            int bB = mB >> 6, nB = mB & 63;
            float2 vA = make_float2(acc[mt][nt][0] + b0, acc[mt][nt][1] + b1);
            float2 vB = make_float2(acc[mt][nt][2] + b0, acc[mt][nt][3] + b1);
            *(float2*)(Dst + (((size_t)(bA * H_ + hh)) * N_ + nA) * C_ + c) = vA;
            *(float2*)(Dst + (((size_t)(bB * H_ + hh)) * N_ + nB) * C_ + c) = vB;
        }
    }
}

// ---------------- skip-mean path --------------------------------------------
__global__ __launch_bounds__(128) void k_xmean() {
    int b = blockIdx.x, t = threadIdx.x;
    float s0 = 0.f, s1 = 0.f;
    for (int n = 0; n < 64; n++) {
        unsigned wh = g_Xph[(size_t)(b * 64 + n) * 128 + t];
        unsigned wl = g_Xpl[(size_t)(b * 64 + n) * 128 + t];
        s0 += up_lo(wh) + up_lo(wl);
        s1 += up_hi(wh) + up_hi(wl);
    }
    g_Xm[b * D_ + 2 * t]     = s0 * (1.f / 64.f);
    g_Xm[b * D_ + 2 * t + 1] = s1 * (1.f / 64.f);
}
__global__ __launch_bounds__(256) void k_skip(const float* __restrict__ Ws,
                                              const float* __restrict__ bs) {
    __shared__ float xm[4][256];
    int b0 = blockIdx.x * 4, t = threadIdx.x;
#pragma unroll
    for (int q = 0; q < 4; q++) xm[q][t] = g_Xm[(size_t)(b0 + q) * D_ + t];
    __syncthreads();
    float a0[4], a1[4];
    float bs0 = bs[t], bs1 = bs[t + 256];
#pragma unroll
    for (int q = 0; q < 4; q++) { a0[q] = bs0; a1[q] = bs1; }
    for (int k = 0; k < 256; k++) {
        float w0 = Ws[(size_t)k * HC_ + t];
        float w1 = Ws[(size_t)k * HC_ + t + 256];
#pragma unroll
        for (int q = 0; q < 4; q++) {
            a0[q] += xm[q][k] * w0;
            a1[q] += xm[q][k] * w1;
        }
    }
#pragma unroll
    for (int q = 0; q < 4; q++) {
        g_SM[(size_t)(b0 + q) * HC_ + t]       = a0[q];
        g_SM[(size_t)(b0 + q) * HC_ + t + 256] = a1[q];
    }
}

// ---------------- K3: attention per (b,h) -----------------------------------
__global__ __launch_bounds__(256) void k_attn3() {
    __shared__ float qs[4096];
    __shared__ float ks[4096];
    __shared__ float Ss[4096];

    const int hb = blockIdx.x, b = hb >> 3, h = hb & 7;
    const size_t base = (size_t)hb * (N_ * C_);
    const int t = threadIdx.x;

    for (int f = t; f < 1024; f += 256) {
        ((float4*)qs)[f] = ((const float4*)(g_Q + base))[f];
        int row = f >> 4, c4 = f & 15;
        *(float4*)(ks + row * 64 + ((c4 ^ (row >> 2)) & 15) * 4) =
            ((const float4*)(g_K + base))[f];
    }
    __syncthreads();

    {
        const int ti = t >> 4, tj = t & 15;
        float acc[4][4];
#pragma unroll
        for (int r = 0; r < 4; r++)
#pragma unroll
            for (int j = 0; j < 4; j++) acc[r][j] = 0.f;
#pragma unroll
        for (int c4 = 0; c4 < 16; c4++) {
            float4 q4[4], k4[4];
#pragma unroll
            for (int r = 0; r < 4; r++)
                q4[r] = *(float4*)(qs + (ti * 4 + r) * 64 + c4 * 4);
#pragma unroll
            for (int j = 0; j < 4; j++)
                k4[j] = *(float4*)(ks + (tj * 4 + j) * 64 + ((c4 ^ tj) & 15) * 4);
#pragma unroll
            for (int r = 0; r < 4; r++)
#pragma unroll
                for (int j = 0; j < 4; j++)
                    acc[r][j] += q4[r].x * k4[j].x + q4[r].y * k4[j].y +
                                 q4[r].z * k4[j].z + q4[r].w * k4[j].w;
        }
#pragma unroll
        for (int r = 0; r < 4; r++)
            *(float4*)(Ss + (ti * 4 + r) * 64 + tj * 4) = make_float4(
                acc[r][0] * 0.125f, acc[r][1] * 0.125f,
                acc[r][2] * 0.125f, acc[r][3] * 0.125f);
    }
    __syncthreads();

    for (int f = t; f < 1024; f += 256)
        ((float4*)qs)[f] = ((const float4*)(g_V + base))[f];
    if (t < 128) ks[t] = 0.f;

    {
        const int w = t >> 5, l = t & 31;
        for (int rr = 0; rr < 8; rr++) {
            int r = w * 8 + rr;
            float s1 = Ss[r * 64 + l], s2 = Ss[r * 64 + l + 32];
            int   c1 = g_cnt[r * 64 + l], c2 = g_cnt[r * 64 + l + 32];
            float v1 = c1 ? s1 : -1e30f;
            float v2 = c2 ? s2 : -1e30f;
            float m = fmaxf(v1, v2);
#pragma unroll
            for (int o = 16; o; o >>= 1)
                m = fmaxf(m, __shfl_xor_sync(0xffffffffu, m, o));
            if (m < -1e29f) m = 0.f;
            float a1 = c1 ? (float)c1 * __expf(s1 - m) : 0.f;
            float a2 = c2 ? (float)c2 * __expf(s2 - m) : 0.f;
            float su = a1 + a2;
#pragma unroll
            for (int o = 16; o; o >>= 1)
                su += __shfl_xor_sync(0xffffffffu, su, o);
            float inv = 1.f / (su + 1e-16f);
            Ss[r * 64 + l]      = a1 * inv;
            Ss[r * 64 + l + 32] = a2 * inv;
        }
    }
    __syncthreads();

    {
        const int c = t & 63, gq = t >> 6;
        float s = 0.f;
#pragma unroll
        for (int r = 0; r < 16; r++) s += Ss[(gq * 16 + r) * 64 + c];
        atomicAdd(&ks[c], s);
    }
    __syncthreads();

    {
        const int c = t & 63, gq = t >> 6;
        float s = 0.f;
#pragma unroll
        for (int r = 0; r < 16; r++) {
            int j = gq * 16 + r;
            s += ks[j] * qs[j * 64 + c];
        }
        atomicAdd(&ks[64 + c], s);
    }
    __syncthreads();
    if (t < 64)
        g_G[(size_t)b * HC_ + h * C_ + t] = ks[64 + t] * (1.f / 64.f);
}

// ---------------- K4: out = (G + SM) @ Wr + br ------------------------------
__global__ __launch_bounds__(192) void k_out(const float* __restrict__ Wr,
                                             const float* __restrict__ br,
                                             float* __restrict__ out) {
    int b = blockIdx.x;
    int o = threadIdx.x >> 5;
    int l = threadIdx.x & 31;
    float s = 0.f;
    for (int c = l; c < HC_; c += 32)
        s += (g_G[(size_t)b * HC_ + c] + g_SM[(size_t)b * HC_ + c]) *
             Wr[c * OUT_ + o];
#pragma unroll
    for (int off = 16; off; off >>= 1)
        s += __shfl_xor_sync(0xffffffffu, s, off);
    if (l == 0) out[b * OUT_ + o] = s + br[o];
}

// ---------------------------------------------------------------------------
extern "C" void kernel_launch(void* const* d_in, const int* in_sizes, int n_in,
                              void* d_out, int out_size) {
    const float* X  = (const float*)d_in[0];
    const int*   ei = (const int*)d_in[1];
    const float* Wp = (const float*)d_in[2];
    const float* bp = (const float*)d_in[3];
    const float* Wq = (const float*)d_in[4];
    const float* bq = (const float*)d_in[5];
    const float* Wk = (const float*)d_in[6];
    const float* bk = (const float*)d_in[7];
    const float* Wv = (const float*)d_in[8];
    const float* bv = (const float*)d_in[9];
    const float* Ws = (const float*)d_in[10];
    const float* bs = (const float*)d_in[11];
    const float* Wr = (const float*)d_in[12];
    const float* br = (const float*)d_in[13];
    float* out = (float*)d_out;

    cudaFuncSetAttribute(k_gemm1n, cudaFuncAttributeMaxDynamicSharedMemorySize,
                         GEMM_SMEM);
    cudaFuncSetAttribute(k_gemm2n, cudaFuncAttributeMaxDynamicSharedMemorySize,
                         GEMM_SMEM);

    k_cnt<<<1, 1024>>>(ei);
    k_prep_wp<<<1024, 256>>>(Wp);
    k_prep_wc<<<768, 256>>>(Wq, Wk, Wv);
    k_gemm1n<<<M_ / 128, 512, GEMM_SMEM>>>(X, bp);
    k_xmean<<<B_, 128>>>();
    k_skip<<<B_ / 4, 256>>>(Ws, bs);
    k_gemm2n<<<dim3(M_ / 128, 6), 512, GEMM_SMEM>>>(bq, bk, bv);
    k_attn3<<<B_ * H_, 256>>>();
    k_out<<<B_, 192>>>(Wr, br, out);
}